// round 12
// baseline (speedup 1.0000x reference)
#include <cuda_runtime.h>
#include <cuda_bf16.h>
#include <math.h>
#include <stdint.h>

// ---------------------------------------------------------------------------
// Mamba3Block on GB300 — round 12: GEMM retiled to 256x128, 1 CTA/SM
// (smem-crossbar-bound analysis: 4x B-fragment reuse). Pipeline as R11.
// ---------------------------------------------------------------------------

namespace {
constexpr int B_   = 2;
constexpr int L_   = 4096;
constexpr int DM   = 1024;
constexpr int DI   = 2048;
constexpr int M_   = B_ * L_;        // 8192
constexpr int NCH  = 64;
constexpr int CH   = L_ / NCH;       // 64
constexpr int TWO_DI = 2 * DI;       // 4096
constexpr int DTR  = 64;
}

// ------------------------- fp32 scratch ------------------------------------
__device__ float g_z [(size_t)M_ * DI];
__device__ float g_y [(size_t)M_ * TWO_DI];   // [yl | yr]
__device__ float g_dc[(size_t)M_ * DI];
__device__ float g_sy[B_ * NCH * DI];
__device__ float g_pp[B_ * NCH * DI];
__device__ float g_qq[B_ * NCH * DI];
__device__ float g_ss[B_ * NCH * DI];

// ------------------------- bf16 split scratch ------------------------------
__device__ __nv_bfloat16 g_h_hi [(size_t)M_ * DM],   g_h_lo [(size_t)M_ * DM];
__device__ __nv_bfloat16 g_xw_hi[(size_t)M_ * DI],   g_xw_lo[(size_t)M_ * DI];
__device__ __nv_bfloat16 g_x_hi [(size_t)M_ * DI],   g_x_lo [(size_t)M_ * DI];
__device__ __nv_bfloat16 g_op_hi[(size_t)M_ * DI],   g_op_lo[(size_t)M_ * DI];
__device__ __nv_bfloat16 g_dl_hi[(size_t)M_ * DTR],  g_dl_lo[(size_t)M_ * DTR];
__device__ __nv_bfloat16 g_w1_hi[(size_t)TWO_DI * DM], g_w1_lo[(size_t)TWO_DI * DM];
__device__ __nv_bfloat16 g_ia_hi[(size_t)DI * DI],   g_ia_lo[(size_t)DI * DI];
__device__ __nv_bfloat16 g_id_hi[(size_t)DI * DI],   g_id_lo[(size_t)DI * DI];
__device__ __nv_bfloat16 g_cw_hi[(size_t)DI * DI],   g_cw_lo[(size_t)DI * DI];
__device__ __nv_bfloat16 g_bt_hi[(size_t)DI * DI],   g_bt_lo[(size_t)DI * DI];
__device__ __nv_bfloat16 g_tt_hi[(size_t)DI * DI],   g_tt_lo[(size_t)DI * DI];
__device__ __nv_bfloat16 g_wc_hi[(size_t)TWO_DI * DI], g_wc_lo[(size_t)TWO_DI * DI]; // [W2 ; G]
__device__ __nv_bfloat16 g_wo_hi[(size_t)DM * DI],   g_wo_lo[(size_t)DM * DI];
__device__ __nv_bfloat16 g_dt_hi[(size_t)DI * DTR],  g_dt_lo[(size_t)DI * DTR];

__device__ __forceinline__ float siluf(float v) { return v / (1.f + expf(-v)); }

__device__ __forceinline__ void split1(float v, __nv_bfloat16& h, __nv_bfloat16& l) {
    h = __float2bfloat16(v);
    l = __float2bfloat16(v - __bfloat162float(h));
}

// --------------------------- PTX helpers ------------------------------------
__device__ __forceinline__ uint32_t cvta_smem(const void* p) {
    uint32_t a;
    asm("{ .reg .u64 t; cvta.to.shared.u64 t, %1; cvt.u32.u64 %0, t; }" : "=r"(a) : "l"(p));
    return a;
}
__device__ __forceinline__ void cp16(uint32_t dst, const void* src) {
    asm volatile("cp.async.cg.shared.global [%0], [%1], 16;" :: "r"(dst), "l"(src) : "memory");
}
__device__ __forceinline__ void cp_commit() {
    asm volatile("cp.async.commit_group;" ::: "memory");
}
template<int N>
__device__ __forceinline__ void cp_wait() {
    asm volatile("cp.async.wait_group %0;" :: "n"(N) : "memory");
}
__device__ __forceinline__ void ldsm4(uint32_t* r, uint32_t addr) {
    asm volatile("ldmatrix.sync.aligned.m8n8.x4.shared.b16 {%0,%1,%2,%3}, [%4];"
                 : "=r"(r[0]), "=r"(r[1]), "=r"(r[2]), "=r"(r[3]) : "r"(addr));
}
__device__ __forceinline__ void mma_bf16(float* d, const uint32_t* a, uint32_t b0, uint32_t b1) {
    asm volatile(
        "mma.sync.aligned.m16n8k16.row.col.f32.bf16.bf16.f32 "
        "{%0,%1,%2,%3}, {%4,%5,%6,%7}, {%8,%9}, {%0,%1,%2,%3};"
        : "+f"(d[0]), "+f"(d[1]), "+f"(d[2]), "+f"(d[3])
        : "r"(a[0]), "r"(a[1]), "r"(a[2]), "r"(a[3]), "r"(b0), "r"(b1));
}
#define SW128(o) ((o) ^ (((o) >> 3) & 0x70))

// =====================  mma.sync bf16x3 GEMM (256x128 tile) ==================
// C[M,N] = fp32( (Ah+Al)[M,K] @ (Bh+Bl)[N,K]^T ), tile 256x128, BK=32, 3 stages.
// 8 warps = 4(M) x 2(N); warp tile 64x64. 1 CTA/SM.
template<int EPI, bool WB, bool WC>
__global__ __launch_bounds__(256, 1)
void gemm_bf16x3(const __nv_bfloat16* __restrict__ Ah, const __nv_bfloat16* __restrict__ Al,
                 int lda, int abase,
                 const __nv_bfloat16* __restrict__ Bh, const __nv_bfloat16* __restrict__ Bl,
                 float* __restrict__ C,
                 __nv_bfloat16* __restrict__ Oh, __nv_bfloat16* __restrict__ Ol,
                 int ldo, int obase,
                 const float* __restrict__ v1, const float* __restrict__ v2,
                 int N, int K)
{
    constexpr int STAGE_BYTES = 48 * 1024;   // A 32K + B 16K
    extern __shared__ __align__(1024) char sm_raw[];

    const int tid = threadIdx.x;
    const int wid = tid >> 5;
    const int l   = tid & 31;
    const int wm  = wid >> 1;          // 0..3  (M, 64 rows each)
    const int wn  = wid & 1;           // 0..1  (N, 64 cols each)
    const int bm  = blockIdx.y * 256;
    const int bn  = blockIdx.x * 128;
    const uint32_t sb = cvta_smem(sm_raw);

    const int KT = K >> 5;

    const int ldRow = tid >> 3;        // 0..31
    const int ldCh  = tid & 7;
    auto load_tile = [&](int kt, int st) {
        const uint32_t aBase = sb + st * STAGE_BYTES;
        const uint32_t bBase = aBase + 32 * 1024;
        const int kof = kt * 32 + (ldCh & 3) * 8;
        const bool lo = ldCh >= 4;
        #pragma unroll
        for (int i = 0; i < 8; i++) {          // A: 256 rows
            const int r = ldRow + i * 32;
            const uint32_t so = SW128((uint32_t)(r * 128 + ldCh * 16));
            cp16(aBase + so, (lo ? Al : Ah) + (size_t)(bm + r) * lda + abase + kof);
        }
        #pragma unroll
        for (int i = 0; i < 4; i++) {          // B: 128 rows
            const int r = ldRow + i * 32;
            const uint32_t so = SW128((uint32_t)(r * 128 + ldCh * 16));
            cp16(bBase + so, (lo ? Bl : Bh) + (size_t)(bn + r) * K + kof);
        }
        cp_commit();
    };

    int aRow[4], aXr[4];
    #pragma unroll
    for (int mf = 0; mf < 4; mf++) {
        aRow[mf] = wm * 64 + mf * 16 + ((l >> 3) & 1) * 8 + (l & 7);
        aXr[mf]  = (aRow[mf] & 7) << 4;
    }
    const int aChunk = ((l >> 4) & 1) * 16;
    int bRow[4], bXr[4];
    #pragma unroll
    for (int p = 0; p < 4; p++) {
        bRow[p] = wn * 64 + p * 16 + ((l >> 4) & 1) * 8 + (l & 7);
        bXr[p]  = (bRow[p] & 7) << 4;
    }
    const int bChunk = ((l >> 3) & 1) * 16;

    float acc[4][8][4];
    #pragma unroll
    for (int mf = 0; mf < 4; mf++)
        #pragma unroll
        for (int nf = 0; nf < 8; nf++)
            #pragma unroll
            for (int k = 0; k < 4; k++) acc[mf][nf][k] = 0.f;

    load_tile(0, 0);
    if (KT > 1) load_tile(1, 1);

    for (int kt = 0; kt < KT; kt++) {
        if (kt + 2 < KT) cp_wait<1>();
        else             cp_wait<0>();
        __syncthreads();
        if (kt + 2 < KT) load_tile(kt + 2, (kt + 2) % 3);

        const uint32_t aBase = sb + (uint32_t)(kt % 3) * STAGE_BYTES;
        const uint32_t bBase = aBase + 32 * 1024;

        #pragma unroll
        for (int s = 0; s < 2; s++) {
            uint32_t aH[4][4], aL[4][4];
            #pragma unroll
            for (int mf = 0; mf < 4; mf++) {
                ldsm4(aH[mf], aBase + aRow[mf] * 128 + (uint32_t)(((0 << 6) | (s << 5) | aChunk) ^ aXr[mf]));
                ldsm4(aL[mf], aBase + aRow[mf] * 128 + (uint32_t)(((1 << 6) | (s << 5) | aChunk) ^ aXr[mf]));
            }
            #pragma unroll
            for (int p = 0; p < 4; p++) {
                uint32_t rH[4], rL[4];
                ldsm4(rH, bBase + bRow[p] * 128 + (uint32_t)(((0 << 6) | (s << 5) | bChunk) ^ bXr[p]));
                ldsm4(rL, bBase + bRow[p] * 128 + (uint32_t)(((1 << 6) | (s << 5) | bChunk) ^ bXr[p]));
                #pragma unroll
                for (int mf = 0; mf < 4; mf++) {
                    mma_bf16(acc[mf][2 * p],     aH[mf], rH[0], rH[1]);
                    mma_bf16(acc[mf][2 * p + 1], aH[mf], rH[2], rH[3]);
                    mma_bf16(acc[mf][2 * p],     aH[mf], rL[0], rL[1]);
                    mma_bf16(acc[mf][2 * p + 1], aH[mf], rL[2], rL[3]);
                    mma_bf16(acc[mf][2 * p],     aL[mf], rH[0], rH[1]);
                    mma_bf16(acc[mf][2 * p + 1], aL[mf], rH[2], rH[3]);
                }
            }
        }
    }

    const int g   = l >> 2;
    const int tig = l & 3;
    #pragma unroll
    for (int mf = 0; mf < 4; mf++) {
        #pragma unroll
        for (int half = 0; half < 2; half++) {
            const int row = bm + wm * 64 + mf * 16 + g + half * 8;
            #pragma unroll
            for (int nf = 0; nf < 8; nf++) {
                const int col = bn + wn * 64 + nf * 8 + tig * 2;
                float vx = acc[mf][nf][2 * half + 0];
                float vy = acc[mf][nf][2 * half + 1];
                if constexpr (EPI == 3) {
                    float tx = vx + v1[col], ty = vy + v1[col + 1];
                    float sx = (tx > 20.f) ? tx : log1pf(expf(tx));
                    float sy = (ty > 20.f) ? ty : log1pf(expf(ty));
                    vx = expf(-expf(v2[col]) * sx);
                    vy = expf(-expf(v2[col + 1]) * sy);
                }
                if constexpr (WC) {
                    *reinterpret_cast<float2*>(C + (size_t)row * N + col) = make_float2(vx, vy);
                }
                if constexpr (WB) {
                    const size_t o = (size_t)row * ldo + obase + col;
                    __nv_bfloat162 hv = __float22bfloat162_rn(make_float2(vx, vy));
                    float2 hf = __bfloat1622float2(hv);
                    __nv_bfloat162 lv = __float22bfloat162_rn(make_float2(vx - hf.x, vy - hf.y));
                    *reinterpret_cast<__nv_bfloat162*>(Oh + o) = hv;
                    *reinterpret_cast<__nv_bfloat162*>(Ol + o) = lv;
                }
            }
        }
    }
}

// -------------------- fp32 -> bf16 hi/lo strided split ----------------------
__global__ void split_strided_kernel(const float* __restrict__ src,
                                     __nv_bfloat16* __restrict__ hi,
                                     __nv_bfloat16* __restrict__ lo,
                                     int rowlen, int ld, int colofs, int n4)
{
    int i = blockIdx.x * blockDim.x + threadIdx.x;
    if (i >= n4) return;
    float4 v = reinterpret_cast<const float4*>(src)[i];
    int e = i * 4;
    int row = e / rowlen;
    int col = e - row * rowlen;
    size_t o = (size_t)row * ld + colofs + col;
    __nv_bfloat162 h0 = __float22bfloat162_rn(make_float2(v.x, v.y));
    __nv_bfloat162 h1 = __float22bfloat162_rn(make_float2(v.z, v.w));
    float2 f0 = __bfloat1622float2(h0);
    float2 f1 = __bfloat1622float2(h1);
    __nv_bfloat162 l0 = __float22bfloat162_rn(make_float2(v.x - f0.x, v.y - f0.y));
    __nv_bfloat162 l1 = __float22bfloat162_rn(make_float2(v.z - f1.x, v.w - f1.y));
    *reinterpret_cast<__nv_bfloat162*>(hi + o)     = h0;
    *reinterpret_cast<__nv_bfloat162*>(hi + o + 2) = h1;
    *reinterpret_cast<__nv_bfloat162*>(lo + o)     = l0;
    *reinterpret_cast<__nv_bfloat162*>(lo + o + 2) = l1;
}

// -------------------- fp32 [DI x DI] + I -> bf16 hi/lo split ----------------
__global__ void split_eye_kernel(const float* __restrict__ src,
                                 __nv_bfloat16* __restrict__ hi,
                                 __nv_bfloat16* __restrict__ lo)
{
    int i = blockIdx.x * blockDim.x + threadIdx.x;
    if (i >= DI * DI / 4) return;
    float4 v = reinterpret_cast<const float4*>(src)[i];
    int e = i * 4;
    int row = e / DI;
    int col = e - row * DI;
    if (row == col)     v.x += 1.f;
    if (row == col + 1) v.y += 1.f;
    if (row == col + 2) v.z += 1.f;
    if (row == col + 3) v.w += 1.f;
    __nv_bfloat162 h0 = __float22bfloat162_rn(make_float2(v.x, v.y));
    __nv_bfloat162 h1 = __float22bfloat162_rn(make_float2(v.z, v.w));
    float2 f0 = __bfloat1622float2(h0);
    float2 f1 = __bfloat1622float2(h1);
    __nv_bfloat162 l0 = __float22bfloat162_rn(make_float2(v.x - f0.x, v.y - f0.y));
    __nv_bfloat162 l1 = __float22bfloat162_rn(make_float2(v.z - f1.x, v.w - f1.y));
    size_t o = (size_t)e;
    *reinterpret_cast<__nv_bfloat162*>(hi + o)     = h0;
    *reinterpret_cast<__nv_bfloat162*>(hi + o + 2) = h1;
    *reinterpret_cast<__nv_bfloat162*>(lo + o)     = l0;
    *reinterpret_cast<__nv_bfloat162*>(lo + o + 2) = l1;
}

// -------------------- transpose [DI x DI] + split ---------------------------
__global__ void transpose_split_kernel(const float* __restrict__ src,
                                       __nv_bfloat16* __restrict__ hi,
                                       __nv_bfloat16* __restrict__ lo)
{
    __shared__ float t[32][33];
    int x = blockIdx.x * 32 + threadIdx.x;
    int y = blockIdx.y * 32 + threadIdx.y;
    #pragma unroll
    for (int j = 0; j < 32; j += 8)
        t[threadIdx.y + j][threadIdx.x] = src[(size_t)(y + j) * DI + x];
    __syncthreads();
    int ox = blockIdx.y * 32 + threadIdx.x;
    int oy = blockIdx.x * 32 + threadIdx.y;
    #pragma unroll
    for (int j = 0; j < 32; j += 8) {
        float v = t[threadIdx.x][threadIdx.y + j];
        size_t o = (size_t)(oy + j) * DI + ox;
        split1(v, hi[o], lo[o]);
    }
}

// -------------------- conv + bias + SiLU (batch slice) ----------------------
__global__ void conv_silu_kernel(const float* __restrict__ w, const float* __restrict__ bias, int bb)
{
    int i = blockIdx.x * blockDim.x + threadIdx.x;
    if (i >= L_ * DI) return;
    int c = i % DI;
    int l = i / DI;
    float acc = bias[c];
    #pragma unroll
    for (int k = 0; k < 4; k++) {
        int ll = l - 3 + k;
        if (ll >= 0) {
            size_t o = (size_t)(bb * L_ + ll) * DI + c;
            float xv = __bfloat162float(g_xw_hi[o]) + __bfloat162float(g_xw_lo[o]);
            acc = fmaf(w[c * 4 + k], xv, acc);
        }
    }
    float v = siluf(acc);
    size_t oo = (size_t)(bb * L_ + l) * DI + c;
    split1(v, g_x_hi[oo], g_x_lo[oo]);
}

// ------------------ fused double-scan (cumsum + decay recurrence) -----------
__global__ void fscan_p1(int bb)
{
    int c  = blockIdx.x * blockDim.x + threadIdx.x;
    int ch = blockIdx.y;
    size_t ybase = ((size_t)(bb * L_ + ch * CH)) * TWO_DI + c;
    size_t dbase = ((size_t)(bb * L_ + ch * CH)) * DI + c;
    float cx = 0.f, s = 0.f, q = 0.f, P = 1.f;
    #pragma unroll 4
    for (int i = 0; i < CH; i++) {
        float yl = g_y[ybase + (size_t)i * TWO_DI];
        float yr = g_y[ybase + (size_t)i * TWO_DI + DI];
        float d  = g_dc[dbase + (size_t)i * DI];
        cx += yl;
        float u = cx + yr;
        s = fmaf(d, s, u);
        q = fmaf(d, q, 1.f);
        P *= d;
    }
    int idx = (bb * NCH + ch) * DI + c;
    g_sy[idx] = cx; g_pp[idx] = P; g_qq[idx] = q; g_ss[idx] = s;
}
__global__ void fscan_p3(const float* __restrict__ D_ss, int bb)
{
    int c  = blockIdx.x * blockDim.x + threadIdx.x;
    int ch = blockIdx.y;
    float cx = 0.f, st = 0.f;
    for (int p = 0; p < ch; p++) {
        int idx = (bb * NCH + p) * DI + c;
        st = fmaf(g_pp[idx], st, fmaf(g_qq[idx], cx, g_ss[idx]));
        cx += g_sy[idx];
    }
    int gl0 = bb * L_ + ch * CH;
    size_t ybase = (size_t)gl0 * TWO_DI + c;
    size_t dbase = (size_t)gl0 * DI + c;
    float dss = D_ss[c];
    #pragma unroll 4
    for (int i = 0; i < CH; i++) {
        float yl = g_y[ybase + (size_t)i * TWO_DI];
        float yr = g_y[ybase + (size_t)i * TWO_DI + DI];
        float d  = g_dc[dbase + (size_t)i * DI];
        cx += yl;
        float u = cx + yr;
        st = fmaf(d, st, u);
        float z = g_z[dbase + (size_t)i * DI];
        float v = (st + u * dss) * siluf(z);
        size_t oo = dbase + (size_t)i * DI;
        split1(v, g_op_hi[oo], g_op_lo[oo]);
    }
}

// ------------------------------- launcher ----------------------------------
extern "C" void kernel_launch(void* const* d_in, const int* in_sizes, int n_in,
                              void* d_out, int out_size)
{
    const float* h         = (const float*)d_in[0];
    const float* delta     = (const float*)d_in[1];
    const float* in_proj_w = (const float*)d_in[2];
    const float* conv_w    = (const float*)d_in[3];
    const float* conv_b    = (const float*)d_in[4];
    const float* A_real    = (const float*)d_in[5];
    const float* B_w       = (const float*)d_in[6];
    const float* C_w       = (const float*)d_in[7];
    const float* D_w       = (const float*)d_in[8];
    const float* dt_proj_w = (const float*)d_in[9];
    const float* dt_proj_b = (const float*)d_in[10];
    const float* A_log     = (const float*)d_in[11];
    const float* D_ss      = (const float*)d_in[12];
    const float* out_proj_w= (const float*)d_in[13];
    float* out = (float*)d_out;

    float *z, *y, *dc;
    cudaGetSymbolAddress((void**)&z,  g_z);
    cudaGetSymbolAddress((void**)&y,  g_y);
    cudaGetSymbolAddress((void**)&dc, g_dc);
    __nv_bfloat16 *hH,*hL,*xwH,*xwL,*xH,*xL,*opH,*opL,*dlH,*dlL;
    __nv_bfloat16 *w1H,*w1L,*iaH,*iaL,*idH,*idL,*cwH,*cwL,*btH,*btL,*ttH,*ttL,*wcH,*wcL,*woH,*woL,*dtH,*dtL;
    cudaGetSymbolAddress((void**)&hH,  g_h_hi);  cudaGetSymbolAddress((void**)&hL,  g_h_lo);
    cudaGetSymbolAddress((void**)&xwH, g_xw_hi); cudaGetSymbolAddress((void**)&xwL, g_xw_lo);
    cudaGetSymbolAddress((void**)&xH,  g_x_hi);  cudaGetSymbolAddress((void**)&xL,  g_x_lo);
    cudaGetSymbolAddress((void**)&opH, g_op_hi); cudaGetSymbolAddress((void**)&opL, g_op_lo);
    cudaGetSymbolAddress((void**)&dlH, g_dl_hi); cudaGetSymbolAddress((void**)&dlL, g_dl_lo);
    cudaGetSymbolAddress((void**)&w1H, g_w1_hi); cudaGetSymbolAddress((void**)&w1L, g_w1_lo);
    cudaGetSymbolAddress((void**)&iaH, g_ia_hi); cudaGetSymbolAddress((void**)&iaL, g_ia_lo);
    cudaGetSymbolAddress((void**)&idH, g_id_hi); cudaGetSymbolAddress((void**)&idL, g_id_lo);
    cudaGetSymbolAddress((void**)&cwH, g_cw_hi); cudaGetSymbolAddress((void**)&cwL, g_cw_lo);
    cudaGetSymbolAddress((void**)&btH, g_bt_hi); cudaGetSymbolAddress((void**)&btL, g_bt_lo);
    cudaGetSymbolAddress((void**)&ttH, g_tt_hi); cudaGetSymbolAddress((void**)&ttL, g_tt_lo);
    cudaGetSymbolAddress((void**)&wcH, g_wc_hi); cudaGetSymbolAddress((void**)&wcL, g_wc_lo);
    cudaGetSymbolAddress((void**)&woH, g_wo_hi); cudaGetSymbolAddress((void**)&woL, g_wo_lo);
    cudaGetSymbolAddress((void**)&dtH, g_dt_hi); cudaGetSymbolAddress((void**)&dtL, g_dt_lo);

    constexpr int SMEM = 144 * 1024;
    cudaFuncSetAttribute(gemm_bf16x3<0, false, true>, cudaFuncAttributeMaxDynamicSharedMemorySize, SMEM);
    cudaFuncSetAttribute(gemm_bf16x3<0, true, false>, cudaFuncAttributeMaxDynamicSharedMemorySize, SMEM);
    cudaFuncSetAttribute(gemm_bf16x3<3, false, true>, cudaFuncAttributeMaxDynamicSharedMemorySize, SMEM);

    static cudaStream_t m1 = nullptr, s2 = nullptr, s3 = nullptr;
    static cudaEvent_t  eF = nullptr, eHW = nullptr, eIA = nullptr, eW2 = nullptr,
                        eG = nullptr, eZ = nullptr, eDT = nullptr, eWO = nullptr,
                        eX0 = nullptr, eP1 = nullptr;
    if (m1 == nullptr) {
        cudaStreamCreateWithFlags(&m1, cudaStreamNonBlocking);
        cudaStreamCreateWithFlags(&s2, cudaStreamNonBlocking);
        cudaStreamCreateWithFlags(&s3, cudaStreamNonBlocking);
        cudaEventCreateWithFlags(&eF,  cudaEventDisableTiming);
        cudaEventCreateWithFlags(&eHW, cudaEventDisableTiming);
        cudaEventCreateWithFlags(&eIA, cudaEventDisableTiming);
        cudaEventCreateWithFlags(&eW2, cudaEventDisableTiming);
        cudaEventCreateWithFlags(&eG,  cudaEventDisableTiming);
        cudaEventCreateWithFlags(&eZ,  cudaEventDisableTiming);
        cudaEventCreateWithFlags(&eDT, cudaEventDisableTiming);
        cudaEventCreateWithFlags(&eWO, cudaEventDisableTiming);
        cudaEventCreateWithFlags(&eX0, cudaEventDisableTiming);
        cudaEventCreateWithFlags(&eP1, cudaEventDisableTiming);
    }

    auto splitOn = [&](cudaStream_t st, const float* s, __nv_bfloat16* hi_, __nv_bfloat16* lo_,
                       int rowlen, int ld, int colofs, size_t n) {
        int n4 = (int)(n / 4);
        split_strided_kernel<<<(n4 + 255) / 256, 256, 0, st>>>(s, hi_, lo_, rowlen, ld, colofs, n4);
    };

    const int GYH = L_ / 256;             // 16 M-tiles per batch slice
    const dim3 gScan(DI / 256, NCH);

    // fork
    cudaEventRecord(eF, 0);
    cudaStreamWaitEvent(m1, eF, 0);
    cudaStreamWaitEvent(s2, eF, 0);
    cudaStreamWaitEvent(s3, eF, 0);

    // launches: 0 splith, 1 splitw1, 2 x0-GEMM, 3 z-GEMM (ncu slots 2-5 = GEMMs)
    splitOn(0, h,         hH,  hL,  DM, DM, 0, (size_t)M_ * DM);
    splitOn(0, in_proj_w, w1H, w1L, DM, DM, 0, (size_t)TWO_DI * DM);
    cudaEventRecord(eHW, 0);

    // x0 = h[b0] @ Wx^T -> xw splits (batch 0)
    gemm_bf16x3<0, true, false><<<dim3(DI / 128, GYH), 256, SMEM>>>(
        hH, hL, DM, 0, w1H, w1L, nullptr, xwH, xwL, DI, 0,
        nullptr, nullptr, DI, DM);
    cudaEventRecord(eX0, 0);

    // z = h @ Wz^T (full batch, s3)
    cudaStreamWaitEvent(s3, eHW, 0);
    gemm_bf16x3<0, false, true><<<dim3(DI / 128, M_ / 256), 256, SMEM, s3>>>(
        hH, hL, DM, 0, w1H + (size_t)DI * DM, w1L + (size_t)DI * DM, z,
        nullptr, nullptr, 0, 0, nullptr, nullptr, DI, DM);
    cudaEventRecord(eZ, s3);

    // s2: W2 fold chain
    splitOn(s2, C_w, cwH, cwL, DI, DI, 0, (size_t)DI * DI);
    transpose_split_kernel<<<dim3(DI / 32, DI / 32), dim3(32, 8), 0, s2>>>(B_w, btH, btL);
    split_eye_kernel<<<(DI * DI / 4) / 256, 256, 0, s2>>>(A_real, iaH, iaL);
    cudaEventRecord(eIA, s2);
    gemm_bf16x3<0, true, false><<<dim3(DI / 128, DI / 256), 256, SMEM, s2>>>(
        cwH, cwL, DI, 0, btH, btL, nullptr, ttH, ttL, DI, 0,
        nullptr, nullptr, DI, DI);
    gemm_bf16x3<0, true, false><<<dim3(DI / 128, DI / 256), 256, SMEM, s2>>>(
        ttH, ttL, DI, 0, iaH, iaL, nullptr, wcH, wcL, DI, 0,
        nullptr, nullptr, DI, DI);
    cudaEventRecord(eW2, s2);

    // s3 (cont.): G fold ; decay ; wo split
    split_eye_kernel<<<(DI * DI / 4) / 256, 256, 0, s3>>>(D_w, idH, idL);
    cudaStreamWaitEvent(s3, eIA, 0);
    gemm_bf16x3<0, true, false><<<dim3(DI / 128, DI / 256), 256, SMEM, s3>>>(
        idH, idL, DI, 0, iaH, iaL, nullptr, wcH, wcL, DI, DI * DI,
        nullptr, nullptr, DI, DI);
    cudaEventRecord(eG, s3);
    splitOn(s3, delta,     dlH, dlL, DTR, DTR, 0, (size_t)M_ * DTR);
    splitOn(s3, dt_proj_w, dtH, dtL, DTR, DTR, 0, (size_t)DI * DTR);
    gemm_bf16x3<3, false, true><<<dim3(DI / 128, M_ / 256), 256, SMEM, s3>>>(
        dlH, dlL, DTR, 0, dtH, dtL, dc, nullptr, nullptr, 0, 0,
        dt_proj_b, A_log, DI, DTR);
    cudaEventRecord(eDT, s3);
    splitOn(s3, out_proj_w, woH, woL, DI, DI, 0, (size_t)DM * DI);
    cudaEventRecord(eWO, s3);

    // ---- pipe 1 (batch 1) on m1, staggered after x0 ----
    cudaStreamWaitEvent(m1, eHW, 0);
    cudaStreamWaitEvent(m1, eX0, 0);
    gemm_bf16x3<0, true, false><<<dim3(DI / 128, GYH), 256, SMEM, m1>>>(
        hH + (size_t)L_ * DM, hL + (size_t)L_ * DM, DM, 0, w1H, w1L, nullptr,
        xwH + (size_t)L_ * DI, xwL + (size_t)L_ * DI, DI, 0,
        nullptr, nullptr, DI, DM);
    conv_silu_kernel<<<(L_ * DI) / 256, 256, 0, m1>>>(conv_w, conv_b, 1);
    cudaStreamWaitEvent(m1, eW2, 0);
    cudaStreamWaitEvent(m1, eG, 0);
    gemm_bf16x3<0, false, true><<<dim3(TWO_DI / 128, GYH), 256, SMEM, m1>>>(
        xH + (size_t)L_ * DI, xL + (size_t)L_ * DI, DI, 0, wcH, wcL,
        y + (size_t)L_ * TWO_DI, nullptr, nullptr, 0, 0,
        nullptr, nullptr, TWO_DI, DI);
    cudaStreamWaitEvent(m1, eDT, 0);
    fscan_p1<<<gScan, 256, 0, m1>>>(1);
    cudaStreamWaitEvent(m1, eZ, 0);
    fscan_p3<<<gScan, 256, 0, m1>>>(D_ss, 1);
    cudaStreamWaitEvent(m1, eWO, 0);
    gemm_bf16x3<0, false, true><<<dim3(DM / 128, GYH), 256, SMEM, m1>>>(
        opH + (size_t)L_ * DI, opL + (size_t)L_ * DI, DI, 0, woH, woL,
        out + (size_t)L_ * DM, nullptr, nullptr, 0, 0,
        nullptr, nullptr, DM, DI);
    cudaEventRecord(eP1, m1);

    // ---- pipe 0 (batch 0) on default stream ----
    conv_silu_kernel<<<(L_ * DI) / 256, 256>>>(conv_w, conv_b, 0);
    cudaStreamWaitEvent(0, eW2, 0);
    cudaStreamWaitEvent(0, eG, 0);
    gemm_bf16x3<0, false, true><<<dim3(TWO_DI / 128, GYH), 256, SMEM>>>(
        xH, xL, DI, 0, wcH, wcL, y, nullptr, nullptr, 0, 0,
        nullptr, nullptr, TWO_DI, DI);
    cudaStreamWaitEvent(0, eDT, 0);
    fscan_p1<<<gScan, 256>>>(0);
    cudaStreamWaitEvent(0, eZ, 0);
    fscan_p3<<<gScan, 256>>>(D_ss, 0);
    cudaStreamWaitEvent(0, eWO, 0);
    gemm_bf16x3<0, false, true><<<dim3(DM / 128, GYH), 256, SMEM>>>(
        opH, opL, DI, 0, woH, woL, out, nullptr, nullptr, 0, 0,
        nullptr, nullptr, DM, DI);

    cudaStreamWaitEvent(0, eP1, 0);
}

// round 13
// speedup vs baseline: 1.1734x; 1.1734x over previous
#include <cuda_runtime.h>
#include <cuda_bf16.h>
#include <math.h>
#include <stdint.h>

// ---------------------------------------------------------------------------
// Mamba3Block on GB300 — round 13: R11 GEMM (128x128, 2 CTA/SM) restored;
// x|z projections merged into one N=4096 GEMM per batch with a
// column-conditional epilogue (x -> bf16 splits, z -> fp32).
// ---------------------------------------------------------------------------

namespace {
constexpr int B_   = 2;
constexpr int L_   = 4096;
constexpr int DM   = 1024;
constexpr int DI   = 2048;
constexpr int M_   = B_ * L_;        // 8192
constexpr int NCH  = 64;
constexpr int CH   = L_ / NCH;       // 64
constexpr int TWO_DI = 2 * DI;       // 4096
constexpr int DTR  = 64;
}

// ------------------------- fp32 scratch ------------------------------------
__device__ float g_z [(size_t)M_ * DI];
__device__ float g_y [(size_t)M_ * TWO_DI];   // [yl | yr]
__device__ float g_dc[(size_t)M_ * DI];
__device__ float g_sy[B_ * NCH * DI];
__device__ float g_pp[B_ * NCH * DI];
__device__ float g_qq[B_ * NCH * DI];
__device__ float g_ss[B_ * NCH * DI];

// ------------------------- bf16 split scratch ------------------------------
__device__ __nv_bfloat16 g_h_hi [(size_t)M_ * DM],   g_h_lo [(size_t)M_ * DM];
__device__ __nv_bfloat16 g_xw_hi[(size_t)M_ * DI],   g_xw_lo[(size_t)M_ * DI];  // pre-conv x
__device__ __nv_bfloat16 g_x_hi [(size_t)M_ * DI],   g_x_lo [(size_t)M_ * DI];  // post conv+silu
__device__ __nv_bfloat16 g_op_hi[(size_t)M_ * DI],   g_op_lo[(size_t)M_ * DI];
__device__ __nv_bfloat16 g_dl_hi[(size_t)M_ * DTR],  g_dl_lo[(size_t)M_ * DTR];
__device__ __nv_bfloat16 g_w1_hi[(size_t)TWO_DI * DM], g_w1_lo[(size_t)TWO_DI * DM];
__device__ __nv_bfloat16 g_ia_hi[(size_t)DI * DI],   g_ia_lo[(size_t)DI * DI];   // I + A_real
__device__ __nv_bfloat16 g_id_hi[(size_t)DI * DI],   g_id_lo[(size_t)DI * DI];   // I + D_w
__device__ __nv_bfloat16 g_cw_hi[(size_t)DI * DI],   g_cw_lo[(size_t)DI * DI];   // C_w
__device__ __nv_bfloat16 g_bt_hi[(size_t)DI * DI],   g_bt_lo[(size_t)DI * DI];   // B_w^T
__device__ __nv_bfloat16 g_tt_hi[(size_t)DI * DI],   g_tt_lo[(size_t)DI * DI];   // T = C_w B_w
__device__ __nv_bfloat16 g_wc_hi[(size_t)TWO_DI * DI], g_wc_lo[(size_t)TWO_DI * DI]; // [W2 ; G]
__device__ __nv_bfloat16 g_wo_hi[(size_t)DM * DI],   g_wo_lo[(size_t)DM * DI];
__device__ __nv_bfloat16 g_dt_hi[(size_t)DI * DTR],  g_dt_lo[(size_t)DI * DTR];

__device__ __forceinline__ float siluf(float v) { return v / (1.f + expf(-v)); }

__device__ __forceinline__ void split1(float v, __nv_bfloat16& h, __nv_bfloat16& l) {
    h = __float2bfloat16(v);
    l = __float2bfloat16(v - __bfloat162float(h));
}

// --------------------------- PTX helpers ------------------------------------
__device__ __forceinline__ uint32_t cvta_smem(const void* p) {
    uint32_t a;
    asm("{ .reg .u64 t; cvta.to.shared.u64 t, %1; cvt.u32.u64 %0, t; }" : "=r"(a) : "l"(p));
    return a;
}
__device__ __forceinline__ void cp16(uint32_t dst, const void* src) {
    asm volatile("cp.async.cg.shared.global [%0], [%1], 16;" :: "r"(dst), "l"(src) : "memory");
}
__device__ __forceinline__ void cp_commit() {
    asm volatile("cp.async.commit_group;" ::: "memory");
}
template<int N>
__device__ __forceinline__ void cp_wait() {
    asm volatile("cp.async.wait_group %0;" :: "n"(N) : "memory");
}
__device__ __forceinline__ void ldsm4(uint32_t* r, uint32_t addr) {
    asm volatile("ldmatrix.sync.aligned.m8n8.x4.shared.b16 {%0,%1,%2,%3}, [%4];"
                 : "=r"(r[0]), "=r"(r[1]), "=r"(r[2]), "=r"(r[3]) : "r"(addr));
}
__device__ __forceinline__ void mma_bf16(float* d, const uint32_t* a, uint32_t b0, uint32_t b1) {
    asm volatile(
        "mma.sync.aligned.m16n8k16.row.col.f32.bf16.bf16.f32 "
        "{%0,%1,%2,%3}, {%4,%5,%6,%7}, {%8,%9}, {%0,%1,%2,%3};"
        : "+f"(d[0]), "+f"(d[1]), "+f"(d[2]), "+f"(d[3])
        : "r"(a[0]), "r"(a[1]), "r"(a[2]), "r"(a[3]), "r"(b0), "r"(b1));
}
#define SW128(o) ((o) ^ (((o) >> 3) & 0x70))

// =====================  mma.sync bf16x3 GEMM (128x128, 2 CTA/SM) ============
// C-cols >= nsplit -> fp32 at row*ldc + cbase + (col - nsplit)
// C-cols <  nsplit -> bf16 hi/lo splits at row*ldo + obase + col
// EPI: 0 none; 3 decay epilogue exp(-exp(v2)*softplus(acc+v1)).
template<int EPI>
__global__ __launch_bounds__(256, 2)
void gemm_bf16x3(const __nv_bfloat16* __restrict__ Ah, const __nv_bfloat16* __restrict__ Al,
                 int lda, int abase,
                 const __nv_bfloat16* __restrict__ Bh, const __nv_bfloat16* __restrict__ Bl,
                 float* __restrict__ C, int ldc, int cbase,
                 __nv_bfloat16* __restrict__ Oh, __nv_bfloat16* __restrict__ Ol,
                 int ldo, int obase, int nsplit,
                 const float* __restrict__ v1, const float* __restrict__ v2,
                 int N, int K)
{
    constexpr int STAGE_BYTES = 32 * 1024;   // A 16K + B 16K
    extern __shared__ __align__(1024) char sm_raw[];

    const int tid = threadIdx.x;
    const int wid = tid >> 5;
    const int l   = tid & 31;
    const int wm  = wid >> 1;
    const int wn  = wid & 1;
    const int bm  = blockIdx.y * 128;
    const int bn  = blockIdx.x * 128;
    const uint32_t sb = cvta_smem(sm_raw);

    const int KT = K >> 5;

    const int ldRow = tid >> 3;
    const int ldCh  = tid & 7;
    auto load_tile = [&](int kt, int st) {
        const uint32_t aBase = sb + st * STAGE_BYTES;
        const uint32_t bBase = aBase + 16 * 1024;
        const int kof = kt * 32 + (ldCh & 3) * 8;
        const bool lo = ldCh >= 4;
        #pragma unroll
        for (int i = 0; i < 4; i++) {
            const int r = ldRow + i * 32;
            const uint32_t so = SW128((uint32_t)(r * 128 + ldCh * 16));
            const size_t ga = (size_t)(bm + r) * lda + abase + kof;
            const size_t gb = (size_t)(bn + r) * K + kof;
            cp16(aBase + so, (lo ? Al : Ah) + ga);
            cp16(bBase + so, (lo ? Bl : Bh) + gb);
        }
        cp_commit();
    };

    int aRow[2], aXr[2];
    #pragma unroll
    for (int mf = 0; mf < 2; mf++) {
        aRow[mf] = wm * 32 + mf * 16 + ((l >> 3) & 1) * 8 + (l & 7);
        aXr[mf]  = (aRow[mf] & 7) << 4;
    }
    const int aChunk = ((l >> 4) & 1) * 16;
    int bRow[4], bXr[4];
    #pragma unroll
    for (int p = 0; p < 4; p++) {
        bRow[p] = wn * 64 + p * 16 + ((l >> 4) & 1) * 8 + (l & 7);
        bXr[p]  = (bRow[p] & 7) << 4;
    }
    const int bChunk = ((l >> 3) & 1) * 16;

    float acc[2][8][4];
    #pragma unroll
    for (int mf = 0; mf < 2; mf++)
        #pragma unroll
        for (int nf = 0; nf < 8; nf++)
            #pragma unroll
            for (int k = 0; k < 4; k++) acc[mf][nf][k] = 0.f;

    load_tile(0, 0);
    if (KT > 1) load_tile(1, 1);

    for (int kt = 0; kt < KT; kt++) {
        if (kt + 2 < KT) cp_wait<1>();
        else             cp_wait<0>();
        __syncthreads();
        if (kt + 2 < KT) load_tile(kt + 2, (kt + 2) % 3);

        const uint32_t aBase = sb + (uint32_t)(kt % 3) * STAGE_BYTES;
        const uint32_t bBase = aBase + 16 * 1024;

        #pragma unroll
        for (int s = 0; s < 2; s++) {
            uint32_t aH[2][4], aL[2][4];
            #pragma unroll
            for (int mf = 0; mf < 2; mf++) {
                ldsm4(aH[mf], aBase + aRow[mf] * 128 + (uint32_t)(((0 << 6) | (s << 5) | aChunk) ^ aXr[mf]));
                ldsm4(aL[mf], aBase + aRow[mf] * 128 + (uint32_t)(((1 << 6) | (s << 5) | aChunk) ^ aXr[mf]));
            }
            #pragma unroll
            for (int p = 0; p < 4; p++) {
                uint32_t rH[4], rL[4];
                ldsm4(rH, bBase + bRow[p] * 128 + (uint32_t)(((0 << 6) | (s << 5) | bChunk) ^ bXr[p]));
                ldsm4(rL, bBase + bRow[p] * 128 + (uint32_t)(((1 << 6) | (s << 5) | bChunk) ^ bXr[p]));
                #pragma unroll
                for (int mf = 0; mf < 2; mf++) {
                    mma_bf16(acc[mf][2 * p],     aH[mf], rH[0], rH[1]);
                    mma_bf16(acc[mf][2 * p + 1], aH[mf], rH[2], rH[3]);
                    mma_bf16(acc[mf][2 * p],     aH[mf], rL[0], rL[1]);
                    mma_bf16(acc[mf][2 * p + 1], aH[mf], rL[2], rL[3]);
                    mma_bf16(acc[mf][2 * p],     aL[mf], rH[0], rH[1]);
                    mma_bf16(acc[mf][2 * p + 1], aL[mf], rH[2], rH[3]);
                }
            }
        }
    }

    const int g   = l >> 2;
    const int tig = l & 3;
    const bool wsplit = bn < nsplit;   // uniform per block (nsplit multiple of 128)
    #pragma unroll
    for (int mf = 0; mf < 2; mf++) {
        #pragma unroll
        for (int half = 0; half < 2; half++) {
            const int row = bm + wm * 32 + mf * 16 + g + half * 8;
            #pragma unroll
            for (int nf = 0; nf < 8; nf++) {
                const int col = bn + wn * 64 + nf * 8 + tig * 2;
                float vx = acc[mf][nf][2 * half + 0];
                float vy = acc[mf][nf][2 * half + 1];
                if constexpr (EPI == 3) {
                    float tx = vx + v1[col], ty = vy + v1[col + 1];
                    float sx = (tx > 20.f) ? tx : log1pf(expf(tx));
                    float sy = (ty > 20.f) ? ty : log1pf(expf(ty));
                    vx = expf(-expf(v2[col]) * sx);
                    vy = expf(-expf(v2[col + 1]) * sy);
                }
                if (wsplit) {
                    const size_t o = (size_t)row * ldo + obase + col;
                    __nv_bfloat162 hv = __float22bfloat162_rn(make_float2(vx, vy));
                    float2 hf = __bfloat1622float2(hv);
                    __nv_bfloat162 lv = __float22bfloat162_rn(make_float2(vx - hf.x, vy - hf.y));
                    *reinterpret_cast<__nv_bfloat162*>(Oh + o) = hv;
                    *reinterpret_cast<__nv_bfloat162*>(Ol + o) = lv;
                } else {
                    *reinterpret_cast<float2*>(C + (size_t)row * ldc + cbase + (col - nsplit))
                        = make_float2(vx, vy);
                }
            }
        }
    }
}

// -------------------- fp32 -> bf16 hi/lo strided split ----------------------
__global__ void split_strided_kernel(const float* __restrict__ src,
                                     __nv_bfloat16* __restrict__ hi,
                                     __nv_bfloat16* __restrict__ lo,
                                     int rowlen, int ld, int colofs, int n4)
{
    int i = blockIdx.x * blockDim.x + threadIdx.x;
    if (i >= n4) return;
    float4 v = reinterpret_cast<const float4*>(src)[i];
    int e = i * 4;
    int row = e / rowlen;
    int col = e - row * rowlen;
    size_t o = (size_t)row * ld + colofs + col;
    __nv_bfloat162 h0 = __float22bfloat162_rn(make_float2(v.x, v.y));
    __nv_bfloat162 h1 = __float22bfloat162_rn(make_float2(v.z, v.w));
    float2 f0 = __bfloat1622float2(h0);
    float2 f1 = __bfloat1622float2(h1);
    __nv_bfloat162 l0 = __float22bfloat162_rn(make_float2(v.x - f0.x, v.y - f0.y));
    __nv_bfloat162 l1 = __float22bfloat162_rn(make_float2(v.z - f1.x, v.w - f1.y));
    *reinterpret_cast<__nv_bfloat162*>(hi + o)     = h0;
    *reinterpret_cast<__nv_bfloat162*>(hi + o + 2) = h1;
    *reinterpret_cast<__nv_bfloat162*>(lo + o)     = l0;
    *reinterpret_cast<__nv_bfloat162*>(lo + o + 2) = l1;
}

// -------------------- fp32 [DI x DI] + I -> bf16 hi/lo split ----------------
__global__ void split_eye_kernel(const float* __restrict__ src,
                                 __nv_bfloat16* __restrict__ hi,
                                 __nv_bfloat16* __restrict__ lo)
{
    int i = blockIdx.x * blockDim.x + threadIdx.x;
    if (i >= DI * DI / 4) return;
    float4 v = reinterpret_cast<const float4*>(src)[i];
    int e = i * 4;
    int row = e / DI;
    int col = e - row * DI;
    if (row == col)     v.x += 1.f;
    if (row == col + 1) v.y += 1.f;
    if (row == col + 2) v.z += 1.f;
    if (row == col + 3) v.w += 1.f;
    __nv_bfloat162 h0 = __float22bfloat162_rn(make_float2(v.x, v.y));
    __nv_bfloat162 h1 = __float22bfloat162_rn(make_float2(v.z, v.w));
    float2 f0 = __bfloat1622float2(h0);
    float2 f1 = __bfloat1622float2(h1);
    __nv_bfloat162 l0 = __float22bfloat162_rn(make_float2(v.x - f0.x, v.y - f0.y));
    __nv_bfloat162 l1 = __float22bfloat162_rn(make_float2(v.z - f1.x, v.w - f1.y));
    size_t o = (size_t)e;
    *reinterpret_cast<__nv_bfloat162*>(hi + o)     = h0;
    *reinterpret_cast<__nv_bfloat162*>(hi + o + 2) = h1;
    *reinterpret_cast<__nv_bfloat162*>(lo + o)     = l0;
    *reinterpret_cast<__nv_bfloat162*>(lo + o + 2) = l1;
}

// -------------------- transpose [DI x DI] + split ---------------------------
__global__ void transpose_split_kernel(const float* __restrict__ src,
                                       __nv_bfloat16* __restrict__ hi,
                                       __nv_bfloat16* __restrict__ lo)
{
    __shared__ float t[32][33];
    int x = blockIdx.x * 32 + threadIdx.x;
    int y = blockIdx.y * 32 + threadIdx.y;
    #pragma unroll
    for (int j = 0; j < 32; j += 8)
        t[threadIdx.y + j][threadIdx.x] = src[(size_t)(y + j) * DI + x];
    __syncthreads();
    int ox = blockIdx.y * 32 + threadIdx.x;
    int oy = blockIdx.x * 32 + threadIdx.y;
    #pragma unroll
    for (int j = 0; j < 32; j += 8) {
        float v = t[threadIdx.x][threadIdx.y + j];
        size_t o = (size_t)(oy + j) * DI + ox;
        split1(v, hi[o], lo[o]);
    }
}

// -------------------- conv + bias + SiLU (batch slice) ----------------------
__global__ void conv_silu_kernel(const float* __restrict__ w, const float* __restrict__ bias, int bb)
{
    int i = blockIdx.x * blockDim.x + threadIdx.x;
    if (i >= L_ * DI) return;
    int c = i % DI;
    int l = i / DI;
    float acc = bias[c];
    #pragma unroll
    for (int k = 0; k < 4; k++) {
        int ll = l - 3 + k;
        if (ll >= 0) {
            size_t o = (size_t)(bb * L_ + ll) * DI + c;
            float xv = __bfloat162float(g_xw_hi[o]) + __bfloat162float(g_xw_lo[o]);
            acc = fmaf(w[c * 4 + k], xv, acc);
        }
    }
    float v = siluf(acc);
    size_t oo = (size_t)(bb * L_ + l) * DI + c;
    split1(v, g_x_hi[oo], g_x_lo[oo]);
}

// ------------------ fused double-scan (cumsum + decay recurrence) -----------
__global__ void fscan_p1(int bb)
{
    int c  = blockIdx.x * blockDim.x + threadIdx.x;
    int ch = blockIdx.y;
    size_t ybase = ((size_t)(bb * L_ + ch * CH)) * TWO_DI + c;
    size_t dbase = ((size_t)(bb * L_ + ch * CH)) * DI + c;
    float cx = 0.f, s = 0.f, q = 0.f, P = 1.f;
    #pragma unroll 4
    for (int i = 0; i < CH; i++) {
        float yl = g_y[ybase + (size_t)i * TWO_DI];
        float yr = g_y[ybase + (size_t)i * TWO_DI + DI];
        float d  = g_dc[dbase + (size_t)i * DI];
        cx += yl;
        float u = cx + yr;
        s = fmaf(d, s, u);
        q = fmaf(d, q, 1.f);
        P *= d;
    }
    int idx = (bb * NCH + ch) * DI + c;
    g_sy[idx] = cx; g_pp[idx] = P; g_qq[idx] = q; g_ss[idx] = s;
}
__global__ void fscan_p3(const float* __restrict__ D_ss, int bb)
{
    int c  = blockIdx.x * blockDim.x + threadIdx.x;
    int ch = blockIdx.y;
    float cx = 0.f, st = 0.f;
    for (int p = 0; p < ch; p++) {
        int idx = (bb * NCH + p) * DI + c;
        st = fmaf(g_pp[idx], st, fmaf(g_qq[idx], cx, g_ss[idx]));
        cx += g_sy[idx];
    }
    int gl0 = bb * L_ + ch * CH;
    size_t ybase = (size_t)gl0 * TWO_DI + c;
    size_t dbase = (size_t)gl0 * DI + c;
    float dss = D_ss[c];
    #pragma unroll 4
    for (int i = 0; i < CH; i++) {
        float yl = g_y[ybase + (size_t)i * TWO_DI];
        float yr = g_y[ybase + (size_t)i * TWO_DI + DI];
        float d  = g_dc[dbase + (size_t)i * DI];
        cx += yl;
        float u = cx + yr;
        st = fmaf(d, st, u);
        float z = g_z[dbase + (size_t)i * DI];
        float v = (st + u * dss) * siluf(z);
        size_t oo = dbase + (size_t)i * DI;
        split1(v, g_op_hi[oo], g_op_lo[oo]);
    }
}

// ------------------------------- launcher ----------------------------------
extern "C" void kernel_launch(void* const* d_in, const int* in_sizes, int n_in,
                              void* d_out, int out_size)
{
    const float* h         = (const float*)d_in[0];
    const float* delta     = (const float*)d_in[1];
    const float* in_proj_w = (const float*)d_in[2];
    const float* conv_w    = (const float*)d_in[3];
    const float* conv_b    = (const float*)d_in[4];
    const float* A_real    = (const float*)d_in[5];
    const float* B_w       = (const float*)d_in[6];
    const float* C_w       = (const float*)d_in[7];
    const float* D_w       = (const float*)d_in[8];
    const float* dt_proj_w = (const float*)d_in[9];
    const float* dt_proj_b = (const float*)d_in[10];
    const float* A_log     = (const float*)d_in[11];
    const float* D_ss      = (const float*)d_in[12];
    const float* out_proj_w= (const float*)d_in[13];
    float* out = (float*)d_out;

    float *z, *y, *dc;
    cudaGetSymbolAddress((void**)&z,  g_z);
    cudaGetSymbolAddress((void**)&y,  g_y);
    cudaGetSymbolAddress((void**)&dc, g_dc);
    __nv_bfloat16 *hH,*hL,*xwH,*xwL,*xH,*xL,*opH,*opL,*dlH,*dlL;
    __nv_bfloat16 *w1H,*w1L,*iaH,*iaL,*idH,*idL,*cwH,*cwL,*btH,*btL,*ttH,*ttL,*wcH,*wcL,*woH,*woL,*dtH,*dtL;
    cudaGetSymbolAddress((void**)&hH,  g_h_hi);  cudaGetSymbolAddress((void**)&hL,  g_h_lo);
    cudaGetSymbolAddress((void**)&xwH, g_xw_hi); cudaGetSymbolAddress((void**)&xwL, g_xw_lo);
    cudaGetSymbolAddress((void**)&xH,  g_x_hi);  cudaGetSymbolAddress((void**)&xL,  g_x_lo);
    cudaGetSymbolAddress((void**)&opH, g_op_hi); cudaGetSymbolAddress((void**)&opL, g_op_lo);
    cudaGetSymbolAddress((void**)&dlH, g_dl_hi); cudaGetSymbolAddress((void**)&dlL, g_dl_lo);
    cudaGetSymbolAddress((void**)&w1H, g_w1_hi); cudaGetSymbolAddress((void**)&w1L, g_w1_lo);
    cudaGetSymbolAddress((void**)&iaH, g_ia_hi); cudaGetSymbolAddress((void**)&iaL, g_ia_lo);
    cudaGetSymbolAddress((void**)&idH, g_id_hi); cudaGetSymbolAddress((void**)&idL, g_id_lo);
    cudaGetSymbolAddress((void**)&cwH, g_cw_hi); cudaGetSymbolAddress((void**)&cwL, g_cw_lo);
    cudaGetSymbolAddress((void**)&btH, g_bt_hi); cudaGetSymbolAddress((void**)&btL, g_bt_lo);
    cudaGetSymbolAddress((void**)&ttH, g_tt_hi); cudaGetSymbolAddress((void**)&ttL, g_tt_lo);
    cudaGetSymbolAddress((void**)&wcH, g_wc_hi); cudaGetSymbolAddress((void**)&wcL, g_wc_lo);
    cudaGetSymbolAddress((void**)&woH, g_wo_hi); cudaGetSymbolAddress((void**)&woL, g_wo_lo);
    cudaGetSymbolAddress((void**)&dtH, g_dt_hi); cudaGetSymbolAddress((void**)&dtL, g_dt_lo);

    constexpr int SMEM = 96 * 1024;
    cudaFuncSetAttribute(gemm_bf16x3<0>, cudaFuncAttributeMaxDynamicSharedMemorySize, SMEM);
    cudaFuncSetAttribute(gemm_bf16x3<3>, cudaFuncAttributeMaxDynamicSharedMemorySize, SMEM);

    static cudaStream_t m1 = nullptr, s2 = nullptr, s3 = nullptr;
    static cudaEvent_t  eF = nullptr, eHW = nullptr, eIA = nullptr, eW2 = nullptr,
                        eG = nullptr, eDT = nullptr, eWO = nullptr,
                        eX0 = nullptr, eP1 = nullptr;
    if (m1 == nullptr) {
        cudaStreamCreateWithFlags(&m1, cudaStreamNonBlocking);
        cudaStreamCreateWithFlags(&s2, cudaStreamNonBlocking);
        cudaStreamCreateWithFlags(&s3, cudaStreamNonBlocking);
        cudaEventCreateWithFlags(&eF,  cudaEventDisableTiming);
        cudaEventCreateWithFlags(&eHW, cudaEventDisableTiming);
        cudaEventCreateWithFlags(&eIA, cudaEventDisableTiming);
        cudaEventCreateWithFlags(&eW2, cudaEventDisableTiming);
        cudaEventCreateWithFlags(&eG,  cudaEventDisableTiming);
        cudaEventCreateWithFlags(&eDT, cudaEventDisableTiming);
        cudaEventCreateWithFlags(&eWO, cudaEventDisableTiming);
        cudaEventCreateWithFlags(&eX0, cudaEventDisableTiming);
        cudaEventCreateWithFlags(&eP1, cudaEventDisableTiming);
    }

    auto splitOn = [&](cudaStream_t st, const float* s, __nv_bfloat16* hi_, __nv_bfloat16* lo_,
                       int rowlen, int ld, int colofs, size_t n) {
        int n4 = (int)(n / 4);
        split_strided_kernel<<<(n4 + 255) / 256, 256, 0, st>>>(s, hi_, lo_, rowlen, ld, colofs, n4);
    };

    const int GYH = L_ / 128;             // 32 M-tiles per batch slice
    const dim3 gScan(DI / 256, NCH);

    // fork
    cudaEventRecord(eF, 0);
    cudaStreamWaitEvent(m1, eF, 0);
    cudaStreamWaitEvent(s2, eF, 0);
    cudaStreamWaitEvent(s3, eF, 0);

    splitOn(0, h,         hH,  hL,  DM, DM, 0, (size_t)M_ * DM);
    splitOn(0, in_proj_w, w1H, w1L, DM, DM, 0, (size_t)TWO_DI * DM);
    cudaEventRecord(eHW, 0);

    // xz0: [x|z] = h[b0] @ in_proj^T ; x -> xw splits, z -> fp32
    gemm_bf16x3<0><<<dim3(TWO_DI / 128, GYH), 256, SMEM>>>(
        hH, hL, DM, 0, w1H, w1L,
        z, DI, 0, xwH, xwL, DI, 0, DI,
        nullptr, nullptr, TWO_DI, DM);
    cudaEventRecord(eX0, 0);

    // s2: W2 fold chain
    splitOn(s2, C_w, cwH, cwL, DI, DI, 0, (size_t)DI * DI);
    transpose_split_kernel<<<dim3(DI / 32, DI / 32), dim3(32, 8), 0, s2>>>(B_w, btH, btL);
    split_eye_kernel<<<(DI * DI / 4) / 256, 256, 0, s2>>>(A_real, iaH, iaL);
    cudaEventRecord(eIA, s2);
    gemm_bf16x3<0><<<dim3(DI / 128, DI / 128), 256, SMEM, s2>>>(
        cwH, cwL, DI, 0, btH, btL,
        nullptr, 0, 0, ttH, ttL, DI, 0, DI,
        nullptr, nullptr, DI, DI);
    gemm_bf16x3<0><<<dim3(DI / 128, DI / 128), 256, SMEM, s2>>>(
        ttH, ttL, DI, 0, iaH, iaL,
        nullptr, 0, 0, wcH, wcL, DI, 0, DI,
        nullptr, nullptr, DI, DI);
    cudaEventRecord(eW2, s2);

    // s3: G fold ; decay ; wo split
    split_eye_kernel<<<(DI * DI / 4) / 256, 256, 0, s3>>>(D_w, idH, idL);
    cudaStreamWaitEvent(s3, eIA, 0);
    gemm_bf16x3<0><<<dim3(DI / 128, DI / 128), 256, SMEM, s3>>>(
        idH, idL, DI, 0, iaH, iaL,
        nullptr, 0, 0, wcH, wcL, DI, DI * DI, DI,
        nullptr, nullptr, DI, DI);
    cudaEventRecord(eG, s3);
    splitOn(s3, delta,     dlH, dlL, DTR, DTR, 0, (size_t)M_ * DTR);
    splitOn(s3, dt_proj_w, dtH, dtL, DTR, DTR, 0, (size_t)DI * DTR);
    gemm_bf16x3<3><<<dim3(DI / 128, M_ / 128), 256, SMEM, s3>>>(
        dlH, dlL, DTR, 0, dtH, dtL,
        dc, DI, 0, nullptr, nullptr, 0, 0, 0,
        dt_proj_b, A_log, DI, DTR);
    cudaEventRecord(eDT, s3);
    splitOn(s3, out_proj_w, woH, woL, DI, DI, 0, (size_t)DM * DI);
    cudaEventRecord(eWO, s3);

    // ---- pipe 1 (batch 1) on m1, staggered after xz0 ----
    cudaStreamWaitEvent(m1, eHW, 0);
    cudaStreamWaitEvent(m1, eX0, 0);
    gemm_bf16x3<0><<<dim3(TWO_DI / 128, GYH), 256, SMEM, m1>>>(
        hH + (size_t)L_ * DM, hL + (size_t)L_ * DM, DM, 0, w1H, w1L,
        z + (size_t)L_ * DI, DI, 0,
        xwH + (size_t)L_ * DI, xwL + (size_t)L_ * DI, DI, 0, DI,
        nullptr, nullptr, TWO_DI, DM);
    conv_silu_kernel<<<(L_ * DI) / 256, 256, 0, m1>>>(conv_w, conv_b, 1);
    cudaStreamWaitEvent(m1, eW2, 0);
    cudaStreamWaitEvent(m1, eG, 0);
    gemm_bf16x3<0><<<dim3(TWO_DI / 128, GYH), 256, SMEM, m1>>>(
        xH + (size_t)L_ * DI, xL + (size_t)L_ * DI, DI, 0, wcH, wcL,
        y + (size_t)L_ * TWO_DI, TWO_DI, 0, nullptr, nullptr, 0, 0, 0,
        nullptr, nullptr, TWO_DI, DI);
    cudaStreamWaitEvent(m1, eDT, 0);
    fscan_p1<<<gScan, 256, 0, m1>>>(1);
    fscan_p3<<<gScan, 256, 0, m1>>>(D_ss, 1);
    cudaStreamWaitEvent(m1, eWO, 0);
    gemm_bf16x3<0><<<dim3(DM / 128, GYH), 256, SMEM, m1>>>(
        opH + (size_t)L_ * DI, opL + (size_t)L_ * DI, DI, 0, woH, woL,
        out + (size_t)L_ * DM, DM, 0, nullptr, nullptr, 0, 0, 0,
        nullptr, nullptr, DM, DI);
    cudaEventRecord(eP1, m1);

    // ---- pipe 0 (batch 0) on default stream ----
    conv_silu_kernel<<<(L_ * DI) / 256, 256>>>(conv_w, conv_b, 0);
    cudaStreamWaitEvent(0, eW2, 0);
    cudaStreamWaitEvent(0, eG, 0);
    gemm_bf16x3<0><<<dim3(TWO_DI / 128, GYH), 256, SMEM>>>(
        xH, xL, DI, 0, wcH, wcL,
        y, TWO_DI, 0, nullptr, nullptr, 0, 0, 0,
        nullptr, nullptr, TWO_DI, DI);
    cudaStreamWaitEvent(0, eDT, 0);
    fscan_p1<<<gScan, 256>>>(0);
    fscan_p3<<<gScan, 256>>>(D_ss, 0);
    cudaStreamWaitEvent(0, eWO, 0);
    gemm_bf16x3<0><<<dim3(DM / 128, GYH), 256, SMEM>>>(
        opH, opL, DI, 0, woH, woL,
        out, DM, 0, nullptr, nullptr, 0, 0, 0,
        nullptr, nullptr, DM, DI);

    cudaStreamWaitEvent(0, eP1, 0);
}

// round 14
// speedup vs baseline: 1.1792x; 1.0050x over previous
#include <cuda_runtime.h>
#include <cuda_bf16.h>
#include <math.h>
#include <stdint.h>

// ---------------------------------------------------------------------------
// Mamba3Block on GB300 — round 14: y-GEMM split by N-half so y_right (needs
// only G) starts while the serial W2 fold chain finishes. Otherwise R13.
// ---------------------------------------------------------------------------

namespace {
constexpr int B_   = 2;
constexpr int L_   = 4096;
constexpr int DM   = 1024;
constexpr int DI   = 2048;
constexpr int M_   = B_ * L_;        // 8192
constexpr int NCH  = 64;
constexpr int CH   = L_ / NCH;       // 64
constexpr int TWO_DI = 2 * DI;       // 4096
constexpr int DTR  = 64;
}

// ------------------------- fp32 scratch ------------------------------------
__device__ float g_z [(size_t)M_ * DI];
__device__ float g_y [(size_t)M_ * TWO_DI];   // [yl | yr]
__device__ float g_dc[(size_t)M_ * DI];
__device__ float g_sy[B_ * NCH * DI];
__device__ float g_pp[B_ * NCH * DI];
__device__ float g_qq[B_ * NCH * DI];
__device__ float g_ss[B_ * NCH * DI];

// ------------------------- bf16 split scratch ------------------------------
__device__ __nv_bfloat16 g_h_hi [(size_t)M_ * DM],   g_h_lo [(size_t)M_ * DM];
__device__ __nv_bfloat16 g_xw_hi[(size_t)M_ * DI],   g_xw_lo[(size_t)M_ * DI];  // pre-conv x
__device__ __nv_bfloat16 g_x_hi [(size_t)M_ * DI],   g_x_lo [(size_t)M_ * DI];  // post conv+silu
__device__ __nv_bfloat16 g_op_hi[(size_t)M_ * DI],   g_op_lo[(size_t)M_ * DI];
__device__ __nv_bfloat16 g_dl_hi[(size_t)M_ * DTR],  g_dl_lo[(size_t)M_ * DTR];
__device__ __nv_bfloat16 g_w1_hi[(size_t)TWO_DI * DM], g_w1_lo[(size_t)TWO_DI * DM];
__device__ __nv_bfloat16 g_ia_hi[(size_t)DI * DI],   g_ia_lo[(size_t)DI * DI];   // I + A_real
__device__ __nv_bfloat16 g_id_hi[(size_t)DI * DI],   g_id_lo[(size_t)DI * DI];   // I + D_w
__device__ __nv_bfloat16 g_cw_hi[(size_t)DI * DI],   g_cw_lo[(size_t)DI * DI];   // C_w
__device__ __nv_bfloat16 g_bt_hi[(size_t)DI * DI],   g_bt_lo[(size_t)DI * DI];   // B_w^T
__device__ __nv_bfloat16 g_tt_hi[(size_t)DI * DI],   g_tt_lo[(size_t)DI * DI];   // T = C_w B_w
__device__ __nv_bfloat16 g_wc_hi[(size_t)TWO_DI * DI], g_wc_lo[(size_t)TWO_DI * DI]; // rows: [W2 ; G]
__device__ __nv_bfloat16 g_wo_hi[(size_t)DM * DI],   g_wo_lo[(size_t)DM * DI];
__device__ __nv_bfloat16 g_dt_hi[(size_t)DI * DTR],  g_dt_lo[(size_t)DI * DTR];

__device__ __forceinline__ float siluf(float v) { return v / (1.f + expf(-v)); }

__device__ __forceinline__ void split1(float v, __nv_bfloat16& h, __nv_bfloat16& l) {
    h = __float2bfloat16(v);
    l = __float2bfloat16(v - __bfloat162float(h));
}

// --------------------------- PTX helpers ------------------------------------
__device__ __forceinline__ uint32_t cvta_smem(const void* p) {
    uint32_t a;
    asm("{ .reg .u64 t; cvta.to.shared.u64 t, %1; cvt.u32.u64 %0, t; }" : "=r"(a) : "l"(p));
    return a;
}
__device__ __forceinline__ void cp16(uint32_t dst, const void* src) {
    asm volatile("cp.async.cg.shared.global [%0], [%1], 16;" :: "r"(dst), "l"(src) : "memory");
}
__device__ __forceinline__ void cp_commit() {
    asm volatile("cp.async.commit_group;" ::: "memory");
}
template<int N>
__device__ __forceinline__ void cp_wait() {
    asm volatile("cp.async.wait_group %0;" :: "n"(N) : "memory");
}
__device__ __forceinline__ void ldsm4(uint32_t* r, uint32_t addr) {
    asm volatile("ldmatrix.sync.aligned.m8n8.x4.shared.b16 {%0,%1,%2,%3}, [%4];"
                 : "=r"(r[0]), "=r"(r[1]), "=r"(r[2]), "=r"(r[3]) : "r"(addr));
}
__device__ __forceinline__ void mma_bf16(float* d, const uint32_t* a, uint32_t b0, uint32_t b1) {
    asm volatile(
        "mma.sync.aligned.m16n8k16.row.col.f32.bf16.bf16.f32 "
        "{%0,%1,%2,%3}, {%4,%5,%6,%7}, {%8,%9}, {%0,%1,%2,%3};"
        : "+f"(d[0]), "+f"(d[1]), "+f"(d[2]), "+f"(d[3])
        : "r"(a[0]), "r"(a[1]), "r"(a[2]), "r"(a[3]), "r"(b0), "r"(b1));
}
#define SW128(o) ((o) ^ (((o) >> 3) & 0x70))

// =====================  mma.sync bf16x3 GEMM (128x128, 2 CTA/SM) ============
// C-cols >= nsplit -> fp32 at row*ldc + cbase + (col - nsplit)
// C-cols <  nsplit -> bf16 hi/lo splits at row*ldo + obase + col
// EPI: 0 none; 3 decay epilogue exp(-exp(v2)*softplus(acc+v1)).
template<int EPI>
__global__ __launch_bounds__(256, 2)
void gemm_bf16x3(const __nv_bfloat16* __restrict__ Ah, const __nv_bfloat16* __restrict__ Al,
                 int lda, int abase,
                 const __nv_bfloat16* __restrict__ Bh, const __nv_bfloat16* __restrict__ Bl,
                 float* __restrict__ C, int ldc, int cbase,
                 __nv_bfloat16* __restrict__ Oh, __nv_bfloat16* __restrict__ Ol,
                 int ldo, int obase, int nsplit,
                 const float* __restrict__ v1, const float* __restrict__ v2,
                 int N, int K)
{
    constexpr int STAGE_BYTES = 32 * 1024;   // A 16K + B 16K
    extern __shared__ __align__(1024) char sm_raw[];

    const int tid = threadIdx.x;
    const int wid = tid >> 5;
    const int l   = tid & 31;
    const int wm  = wid >> 1;
    const int wn  = wid & 1;
    const int bm  = blockIdx.y * 128;
    const int bn  = blockIdx.x * 128;
    const uint32_t sb = cvta_smem(sm_raw);

    const int KT = K >> 5;

    const int ldRow = tid >> 3;
    const int ldCh  = tid & 7;
    auto load_tile = [&](int kt, int st) {
        const uint32_t aBase = sb + st * STAGE_BYTES;
        const uint32_t bBase = aBase + 16 * 1024;
        const int kof = kt * 32 + (ldCh & 3) * 8;
        const bool lo = ldCh >= 4;
        #pragma unroll
        for (int i = 0; i < 4; i++) {
            const int r = ldRow + i * 32;
            const uint32_t so = SW128((uint32_t)(r * 128 + ldCh * 16));
            const size_t ga = (size_t)(bm + r) * lda + abase + kof;
            const size_t gb = (size_t)(bn + r) * K + kof;
            cp16(aBase + so, (lo ? Al : Ah) + ga);
            cp16(bBase + so, (lo ? Bl : Bh) + gb);
        }
        cp_commit();
    };

    int aRow[2], aXr[2];
    #pragma unroll
    for (int mf = 0; mf < 2; mf++) {
        aRow[mf] = wm * 32 + mf * 16 + ((l >> 3) & 1) * 8 + (l & 7);
        aXr[mf]  = (aRow[mf] & 7) << 4;
    }
    const int aChunk = ((l >> 4) & 1) * 16;
    int bRow[4], bXr[4];
    #pragma unroll
    for (int p = 0; p < 4; p++) {
        bRow[p] = wn * 64 + p * 16 + ((l >> 4) & 1) * 8 + (l & 7);
        bXr[p]  = (bRow[p] & 7) << 4;
    }
    const int bChunk = ((l >> 3) & 1) * 16;

    float acc[2][8][4];
    #pragma unroll
    for (int mf = 0; mf < 2; mf++)
        #pragma unroll
        for (int nf = 0; nf < 8; nf++)
            #pragma unroll
            for (int k = 0; k < 4; k++) acc[mf][nf][k] = 0.f;

    load_tile(0, 0);
    if (KT > 1) load_tile(1, 1);

    for (int kt = 0; kt < KT; kt++) {
        if (kt + 2 < KT) cp_wait<1>();
        else             cp_wait<0>();
        __syncthreads();
        if (kt + 2 < KT) load_tile(kt + 2, (kt + 2) % 3);

        const uint32_t aBase = sb + (uint32_t)(kt % 3) * STAGE_BYTES;
        const uint32_t bBase = aBase + 16 * 1024;

        #pragma unroll
        for (int s = 0; s < 2; s++) {
            uint32_t aH[2][4], aL[2][4];
            #pragma unroll
            for (int mf = 0; mf < 2; mf++) {
                ldsm4(aH[mf], aBase + aRow[mf] * 128 + (uint32_t)(((0 << 6) | (s << 5) | aChunk) ^ aXr[mf]));
                ldsm4(aL[mf], aBase + aRow[mf] * 128 + (uint32_t)(((1 << 6) | (s << 5) | aChunk) ^ aXr[mf]));
            }
            #pragma unroll
            for (int p = 0; p < 4; p++) {
                uint32_t rH[4], rL[4];
                ldsm4(rH, bBase + bRow[p] * 128 + (uint32_t)(((0 << 6) | (s << 5) | bChunk) ^ bXr[p]));
                ldsm4(rL, bBase + bRow[p] * 128 + (uint32_t)(((1 << 6) | (s << 5) | bChunk) ^ bXr[p]));
                #pragma unroll
                for (int mf = 0; mf < 2; mf++) {
                    mma_bf16(acc[mf][2 * p],     aH[mf], rH[0], rH[1]);
                    mma_bf16(acc[mf][2 * p + 1], aH[mf], rH[2], rH[3]);
                    mma_bf16(acc[mf][2 * p],     aH[mf], rL[0], rL[1]);
                    mma_bf16(acc[mf][2 * p + 1], aH[mf], rL[2], rL[3]);
                    mma_bf16(acc[mf][2 * p],     aL[mf], rH[0], rH[1]);
                    mma_bf16(acc[mf][2 * p + 1], aL[mf], rH[2], rH[3]);
                }
            }
        }
    }

    const int g   = l >> 2;
    const int tig = l & 3;
    const bool wsplit = bn < nsplit;
    #pragma unroll
    for (int mf = 0; mf < 2; mf++) {
        #pragma unroll
        for (int half = 0; half < 2; half++) {
            const int row = bm + wm * 32 + mf * 16 + g + half * 8;
            #pragma unroll
            for (int nf = 0; nf < 8; nf++) {
                const int col = bn + wn * 64 + nf * 8 + tig * 2;
                float vx = acc[mf][nf][2 * half + 0];
                float vy = acc[mf][nf][2 * half + 1];
                if constexpr (EPI == 3) {
                    float tx = vx + v1[col], ty = vy + v1[col + 1];
                    float sx = (tx > 20.f) ? tx : log1pf(expf(tx));
                    float sy = (ty > 20.f) ? ty : log1pf(expf(ty));
                    vx = expf(-expf(v2[col]) * sx);
                    vy = expf(-expf(v2[col + 1]) * sy);
                }
                if (wsplit) {
                    const size_t o = (size_t)row * ldo + obase + col;
                    __nv_bfloat162 hv = __float22bfloat162_rn(make_float2(vx, vy));
                    float2 hf = __bfloat1622float2(hv);
                    __nv_bfloat162 lv = __float22bfloat162_rn(make_float2(vx - hf.x, vy - hf.y));
                    *reinterpret_cast<__nv_bfloat162*>(Oh + o) = hv;
                    *reinterpret_cast<__nv_bfloat162*>(Ol + o) = lv;
                } else {
                    *reinterpret_cast<float2*>(C + (size_t)row * ldc + cbase + (col - nsplit))
                        = make_float2(vx, vy);
                }
            }
        }
    }
}

// -------------------- fp32 -> bf16 hi/lo strided split ----------------------
__global__ void split_strided_kernel(const float* __restrict__ src,
                                     __nv_bfloat16* __restrict__ hi,
                                     __nv_bfloat16* __restrict__ lo,
                                     int rowlen, int ld, int colofs, int n4)
{
    int i = blockIdx.x * blockDim.x + threadIdx.x;
    if (i >= n4) return;
    float4 v = reinterpret_cast<const float4*>(src)[i];
    int e = i * 4;
    int row = e / rowlen;
    int col = e - row * rowlen;
    size_t o = (size_t)row * ld + colofs + col;
    __nv_bfloat162 h0 = __float22bfloat162_rn(make_float2(v.x, v.y));
    __nv_bfloat162 h1 = __float22bfloat162_rn(make_float2(v.z, v.w));
    float2 f0 = __bfloat1622float2(h0);
    float2 f1 = __bfloat1622float2(h1);
    __nv_bfloat162 l0 = __float22bfloat162_rn(make_float2(v.x - f0.x, v.y - f0.y));
    __nv_bfloat162 l1 = __float22bfloat162_rn(make_float2(v.z - f1.x, v.w - f1.y));
    *reinterpret_cast<__nv_bfloat162*>(hi + o)     = h0;
    *reinterpret_cast<__nv_bfloat162*>(hi + o + 2) = h1;
    *reinterpret_cast<__nv_bfloat162*>(lo + o)     = l0;
    *reinterpret_cast<__nv_bfloat162*>(lo + o + 2) = l1;
}

// -------------------- fp32 [DI x DI] + I -> bf16 hi/lo split ----------------
__global__ void split_eye_kernel(const float* __restrict__ src,
                                 __nv_bfloat16* __restrict__ hi,
                                 __nv_bfloat16* __restrict__ lo)
{
    int i = blockIdx.x * blockDim.x + threadIdx.x;
    if (i >= DI * DI / 4) return;
    float4 v = reinterpret_cast<const float4*>(src)[i];
    int e = i * 4;
    int row = e / DI;
    int col = e - row * DI;
    if (row == col)     v.x += 1.f;
    if (row == col + 1) v.y += 1.f;
    if (row == col + 2) v.z += 1.f;
    if (row == col + 3) v.w += 1.f;
    __nv_bfloat162 h0 = __float22bfloat162_rn(make_float2(v.x, v.y));
    __nv_bfloat162 h1 = __float22bfloat162_rn(make_float2(v.z, v.w));
    float2 f0 = __bfloat1622float2(h0);
    float2 f1 = __bfloat1622float2(h1);
    __nv_bfloat162 l0 = __float22bfloat162_rn(make_float2(v.x - f0.x, v.y - f0.y));
    __nv_bfloat162 l1 = __float22bfloat162_rn(make_float2(v.z - f1.x, v.w - f1.y));
    size_t o = (size_t)e;
    *reinterpret_cast<__nv_bfloat162*>(hi + o)     = h0;
    *reinterpret_cast<__nv_bfloat162*>(hi + o + 2) = h1;
    *reinterpret_cast<__nv_bfloat162*>(lo + o)     = l0;
    *reinterpret_cast<__nv_bfloat162*>(lo + o + 2) = l1;
}

// -------------------- transpose [DI x DI] + split ---------------------------
__global__ void transpose_split_kernel(const float* __restrict__ src,
                                       __nv_bfloat16* __restrict__ hi,
                                       __nv_bfloat16* __restrict__ lo)
{
    __shared__ float t[32][33];
    int x = blockIdx.x * 32 + threadIdx.x;
    int y = blockIdx.y * 32 + threadIdx.y;
    #pragma unroll
    for (int j = 0; j < 32; j += 8)
        t[threadIdx.y + j][threadIdx.x] = src[(size_t)(y + j) * DI + x];
    __syncthreads();
    int ox = blockIdx.y * 32 + threadIdx.x;
    int oy = blockIdx.x * 32 + threadIdx.y;
    #pragma unroll
    for (int j = 0; j < 32; j += 8) {
        float v = t[threadIdx.x][threadIdx.y + j];
        size_t o = (size_t)(oy + j) * DI + ox;
        split1(v, hi[o], lo[o]);
    }
}

// -------------------- conv + bias + SiLU (batch slice) ----------------------
__global__ void conv_silu_kernel(const float* __restrict__ w, const float* __restrict__ bias, int bb)
{
    int i = blockIdx.x * blockDim.x + threadIdx.x;
    if (i >= L_ * DI) return;
    int c = i % DI;
    int l = i / DI;
    float acc = bias[c];
    #pragma unroll
    for (int k = 0; k < 4; k++) {
        int ll = l - 3 + k;
        if (ll >= 0) {
            size_t o = (size_t)(bb * L_ + ll) * DI + c;
            float xv = __bfloat162float(g_xw_hi[o]) + __bfloat162float(g_xw_lo[o]);
            acc = fmaf(w[c * 4 + k], xv, acc);
        }
    }
    float v = siluf(acc);
    size_t oo = (size_t)(bb * L_ + l) * DI + c;
    split1(v, g_x_hi[oo], g_x_lo[oo]);
}

// ------------------ fused double-scan (cumsum + decay recurrence) -----------
__global__ void fscan_p1(int bb)
{
    int c  = blockIdx.x * blockDim.x + threadIdx.x;
    int ch = blockIdx.y;
    size_t ybase = ((size_t)(bb * L_ + ch * CH)) * TWO_DI + c;
    size_t dbase = ((size_t)(bb * L_ + ch * CH)) * DI + c;
    float cx = 0.f, s = 0.f, q = 0.f, P = 1.f;
    #pragma unroll 4
    for (int i = 0; i < CH; i++) {
        float yl = g_y[ybase + (size_t)i * TWO_DI];
        float yr = g_y[ybase + (size_t)i * TWO_DI + DI];
        float d  = g_dc[dbase + (size_t)i * DI];
        cx += yl;
        float u = cx + yr;
        s = fmaf(d, s, u);
        q = fmaf(d, q, 1.f);
        P *= d;
    }
    int idx = (bb * NCH + ch) * DI + c;
    g_sy[idx] = cx; g_pp[idx] = P; g_qq[idx] = q; g_ss[idx] = s;
}
__global__ void fscan_p3(const float* __restrict__ D_ss, int bb)
{
    int c  = blockIdx.x * blockDim.x + threadIdx.x;
    int ch = blockIdx.y;
    float cx = 0.f, st = 0.f;
    for (int p = 0; p < ch; p++) {
        int idx = (bb * NCH + p) * DI + c;
        st = fmaf(g_pp[idx], st, fmaf(g_qq[idx], cx, g_ss[idx]));
        cx += g_sy[idx];
    }
    int gl0 = bb * L_ + ch * CH;
    size_t ybase = (size_t)gl0 * TWO_DI + c;
    size_t dbase = (size_t)gl0 * DI + c;
    float dss = D_ss[c];
    #pragma unroll 4
    for (int i = 0; i < CH; i++) {
        float yl = g_y[ybase + (size_t)i * TWO_DI];
        float yr = g_y[ybase + (size_t)i * TWO_DI + DI];
        float d  = g_dc[dbase + (size_t)i * DI];
        cx += yl;
        float u = cx + yr;
        st = fmaf(d, st, u);
        float z = g_z[dbase + (size_t)i * DI];
        float v = (st + u * dss) * siluf(z);
        size_t oo = dbase + (size_t)i * DI;
        split1(v, g_op_hi[oo], g_op_lo[oo]);
    }
}

// ------------------------------- launcher ----------------------------------
extern "C" void kernel_launch(void* const* d_in, const int* in_sizes, int n_in,
                              void* d_out, int out_size)
{
    const float* h         = (const float*)d_in[0];
    const float* delta     = (const float*)d_in[1];
    const float* in_proj_w = (const float*)d_in[2];
    const float* conv_w    = (const float*)d_in[3];
    const float* conv_b    = (const float*)d_in[4];
    const float* A_real    = (const float*)d_in[5];
    const float* B_w       = (const float*)d_in[6];
    const float* C_w       = (const float*)d_in[7];
    const float* D_w       = (const float*)d_in[8];
    const float* dt_proj_w = (const float*)d_in[9];
    const float* dt_proj_b = (const float*)d_in[10];
    const float* A_log     = (const float*)d_in[11];
    const float* D_ss      = (const float*)d_in[12];
    const float* out_proj_w= (const float*)d_in[13];
    float* out = (float*)d_out;

    float *z, *y, *dc;
    cudaGetSymbolAddress((void**)&z,  g_z);
    cudaGetSymbolAddress((void**)&y,  g_y);
    cudaGetSymbolAddress((void**)&dc, g_dc);
    __nv_bfloat16 *hH,*hL,*xwH,*xwL,*xH,*xL,*opH,*opL,*dlH,*dlL;
    __nv_bfloat16 *w1H,*w1L,*iaH,*iaL,*idH,*idL,*cwH,*cwL,*btH,*btL,*ttH,*ttL,*wcH,*wcL,*woH,*woL,*dtH,*dtL;
    cudaGetSymbolAddress((void**)&hH,  g_h_hi);  cudaGetSymbolAddress((void**)&hL,  g_h_lo);
    cudaGetSymbolAddress((void**)&xwH, g_xw_hi); cudaGetSymbolAddress((void**)&xwL, g_xw_lo);
    cudaGetSymbolAddress((void**)&xH,  g_x_hi);  cudaGetSymbolAddress((void**)&xL,  g_x_lo);
    cudaGetSymbolAddress((void**)&opH, g_op_hi); cudaGetSymbolAddress((void**)&opL, g_op_lo);
    cudaGetSymbolAddress((void**)&dlH, g_dl_hi); cudaGetSymbolAddress((void**)&dlL, g_dl_lo);
    cudaGetSymbolAddress((void**)&w1H, g_w1_hi); cudaGetSymbolAddress((void**)&w1L, g_w1_lo);
    cudaGetSymbolAddress((void**)&iaH, g_ia_hi); cudaGetSymbolAddress((void**)&iaL, g_ia_lo);
    cudaGetSymbolAddress((void**)&idH, g_id_hi); cudaGetSymbolAddress((void**)&idL, g_id_lo);
    cudaGetSymbolAddress((void**)&cwH, g_cw_hi); cudaGetSymbolAddress((void**)&cwL, g_cw_lo);
    cudaGetSymbolAddress((void**)&btH, g_bt_hi); cudaGetSymbolAddress((void**)&btL, g_bt_lo);
    cudaGetSymbolAddress((void**)&ttH, g_tt_hi); cudaGetSymbolAddress((void**)&ttL, g_tt_lo);
    cudaGetSymbolAddress((void**)&wcH, g_wc_hi); cudaGetSymbolAddress((void**)&wcL, g_wc_lo);
    cudaGetSymbolAddress((void**)&woH, g_wo_hi); cudaGetSymbolAddress((void**)&woL, g_wo_lo);
    cudaGetSymbolAddress((void**)&dtH, g_dt_hi); cudaGetSymbolAddress((void**)&dtL, g_dt_lo);

    constexpr int SMEM = 96 * 1024;
    cudaFuncSetAttribute(gemm_bf16x3<0>, cudaFuncAttributeMaxDynamicSharedMemorySize, SMEM);
    cudaFuncSetAttribute(gemm_bf16x3<3>, cudaFuncAttributeMaxDynamicSharedMemorySize, SMEM);

    static cudaStream_t m1 = nullptr, s2 = nullptr, s3 = nullptr;
    static cudaEvent_t  eF = nullptr, eW1 = nullptr, eIA = nullptr, eW2 = nullptr,
                        eG = nullptr, eDT = nullptr, eWO = nullptr,
                        eX0 = nullptr, eP1 = nullptr;
    if (m1 == nullptr) {
        cudaStreamCreateWithFlags(&m1, cudaStreamNonBlocking);
        cudaStreamCreateWithFlags(&s2, cudaStreamNonBlocking);
        cudaStreamCreateWithFlags(&s3, cudaStreamNonBlocking);
        cudaEventCreateWithFlags(&eF,  cudaEventDisableTiming);
        cudaEventCreateWithFlags(&eW1, cudaEventDisableTiming);
        cudaEventCreateWithFlags(&eIA, cudaEventDisableTiming);
        cudaEventCreateWithFlags(&eW2, cudaEventDisableTiming);
        cudaEventCreateWithFlags(&eG,  cudaEventDisableTiming);
        cudaEventCreateWithFlags(&eDT, cudaEventDisableTiming);
        cudaEventCreateWithFlags(&eWO, cudaEventDisableTiming);
        cudaEventCreateWithFlags(&eX0, cudaEventDisableTiming);
        cudaEventCreateWithFlags(&eP1, cudaEventDisableTiming);
    }

    auto splitOn = [&](cudaStream_t st, const float* s, __nv_bfloat16* hi_, __nv_bfloat16* lo_,
                       int rowlen, int ld, int colofs, size_t n) {
        int n4 = (int)(n / 4);
        split_strided_kernel<<<(n4 + 255) / 256, 256, 0, st>>>(s, hi_, lo_, rowlen, ld, colofs, n4);
    };

    const int GYH = L_ / 128;             // 32 M-tiles per batch slice
    const dim3 gScan(DI / 256, NCH);

    // fork
    cudaEventRecord(eF, 0);
    cudaStreamWaitEvent(m1, eF, 0);
    cudaStreamWaitEvent(s2, eF, 0);
    cudaStreamWaitEvent(s3, eF, 0);

    // parallel input splits: h on 0, w1 on m1
    splitOn(0,  h,         hH,  hL,  DM, DM, 0, (size_t)M_ * DM);
    splitOn(m1, in_proj_w, w1H, w1L, DM, DM, 0, (size_t)TWO_DI * DM);
    cudaEventRecord(eW1, m1);
    cudaStreamWaitEvent(0, eW1, 0);

    // xz0: [x|z] = h[b0] @ in_proj^T ; x -> xw splits, z -> fp32
    gemm_bf16x3<0><<<dim3(TWO_DI / 128, GYH), 256, SMEM>>>(
        hH, hL, DM, 0, w1H, w1L,
        z, DI, 0, xwH, xwL, DI, 0, DI,
        nullptr, nullptr, TWO_DI, DM);
    cudaEventRecord(eX0, 0);

    // s2 (short path to G): eye(A) -> eye(D) -> G
    split_eye_kernel<<<(DI * DI / 4) / 256, 256, 0, s2>>>(A_real, iaH, iaL);
    cudaEventRecord(eIA, s2);
    split_eye_kernel<<<(DI * DI / 4) / 256, 256, 0, s2>>>(D_w, idH, idL);
    gemm_bf16x3<0><<<dim3(DI / 128, DI / 128), 256, SMEM, s2>>>(
        idH, idL, DI, 0, iaH, iaL,
        nullptr, 0, 0, wcH, wcL, DI, DI * DI, DI,
        nullptr, nullptr, DI, DI);
    cudaEventRecord(eG, s2);

    // s3: C split, B^T, T = C.B, (wait eIA) W2 = T.(I+A)^T ; then dt, wo
    splitOn(s3, C_w, cwH, cwL, DI, DI, 0, (size_t)DI * DI);
    transpose_split_kernel<<<dim3(DI / 32, DI / 32), dim3(32, 8), 0, s3>>>(B_w, btH, btL);
    gemm_bf16x3<0><<<dim3(DI / 128, DI / 128), 256, SMEM, s3>>>(
        cwH, cwL, DI, 0, btH, btL,
        nullptr, 0, 0, ttH, ttL, DI, 0, DI,
        nullptr, nullptr, DI, DI);
    cudaStreamWaitEvent(s3, eIA, 0);
    gemm_bf16x3<0><<<dim3(DI / 128, DI / 128), 256, SMEM, s3>>>(
        ttH, ttL, DI, 0, iaH, iaL,
        nullptr, 0, 0, wcH, wcL, DI, 0, DI,
        nullptr, nullptr, DI, DI);
    cudaEventRecord(eW2, s3);
    splitOn(s3, delta,     dlH, dlL, DTR, DTR, 0, (size_t)M_ * DTR);
    splitOn(s3, dt_proj_w, dtH, dtL, DTR, DTR, 0, (size_t)DI * DTR);
    gemm_bf16x3<3><<<dim3(DI / 128, M_ / 128), 256, SMEM, s3>>>(
        dlH, dlL, DTR, 0, dtH, dtL,
        dc, DI, 0, nullptr, nullptr, 0, 0, 0,
        dt_proj_b, A_log, DI, DTR);
    cudaEventRecord(eDT, s3);
    splitOn(s3, out_proj_w, woH, woL, DI, DI, 0, (size_t)DM * DI);
    cudaEventRecord(eWO, s3);

    // ---- pipe 1 (batch 1) on m1 ----
    cudaStreamWaitEvent(m1, eX0, 0);
    gemm_bf16x3<0><<<dim3(TWO_DI / 128, GYH), 256, SMEM, m1>>>(
        hH + (size_t)L_ * DM, hL + (size_t)L_ * DM, DM, 0, w1H, w1L,
        z + (size_t)L_ * DI, DI, 0,
        xwH + (size_t)L_ * DI, xwL + (size_t)L_ * DI, DI, 0, DI,
        nullptr, nullptr, TWO_DI, DM);
    conv_silu_kernel<<<(L_ * DI) / 256, 256, 0, m1>>>(conv_w, conv_b, 1);
    // y_right_1 = x1 @ G^T  (needs only eG)
    cudaStreamWaitEvent(m1, eG, 0);
    gemm_bf16x3<0><<<dim3(DI / 128, GYH), 256, SMEM, m1>>>(
        xH + (size_t)L_ * DI, xL + (size_t)L_ * DI, DI, 0,
        wcH + (size_t)DI * DI, wcL + (size_t)DI * DI,
        y + (size_t)L_ * TWO_DI, TWO_DI, DI, nullptr, nullptr, 0, 0, 0,
        nullptr, nullptr, DI, DI);
    // y_left_1 = x1 @ W2^T  (needs eW2)
    cudaStreamWaitEvent(m1, eW2, 0);
    gemm_bf16x3<0><<<dim3(DI / 128, GYH), 256, SMEM, m1>>>(
        xH + (size_t)L_ * DI, xL + (size_t)L_ * DI, DI, 0, wcH, wcL,
        y + (size_t)L_ * TWO_DI, TWO_DI, 0, nullptr, nullptr, 0, 0, 0,
        nullptr, nullptr, DI, DI);
    cudaStreamWaitEvent(m1, eDT, 0);
    fscan_p1<<<gScan, 256, 0, m1>>>(1);
    fscan_p3<<<gScan, 256, 0, m1>>>(D_ss, 1);
    cudaStreamWaitEvent(m1, eWO, 0);
    gemm_bf16x3<0><<<dim3(DM / 128, GYH), 256, SMEM, m1>>>(
        opH + (size_t)L_ * DI, opL + (size_t)L_ * DI, DI, 0, woH, woL,
        out + (size_t)L_ * DM, DM, 0, nullptr, nullptr, 0, 0, 0,
        nullptr, nullptr, DM, DI);
    cudaEventRecord(eP1, m1);

    // ---- pipe 0 (batch 0) on default stream ----
    conv_silu_kernel<<<(L_ * DI) / 256, 256>>>(conv_w, conv_b, 0);
    cudaStreamWaitEvent(0, eG, 0);
    gemm_bf16x3<0><<<dim3(DI / 128, GYH), 256, SMEM>>>(
        xH, xL, DI, 0,
        wcH + (size_t)DI * DI, wcL + (size_t)DI * DI,
        y, TWO_DI, DI, nullptr, nullptr, 0, 0, 0,
        nullptr, nullptr, DI, DI);
    cudaStreamWaitEvent(0, eW2, 0);
    gemm_bf16x3<0><<<dim3(DI / 128, GYH), 256, SMEM>>>(
        xH, xL, DI, 0, wcH, wcL,
        y, TWO_DI, 0, nullptr, nullptr, 0, 0, 0,
        nullptr, nullptr, DI, DI);
    cudaStreamWaitEvent(0, eDT, 0);
    fscan_p1<<<gScan, 256>>>(0);
    fscan_p3<<<gScan, 256>>>(D_ss, 0);
    cudaStreamWaitEvent(0, eWO, 0);
    gemm_bf16x3<0><<<dim3(DM / 128, GYH), 256, SMEM>>>(
        opH, opL, DI, 0, woH, woL,
        out, DM, 0, nullptr, nullptr, 0, 0, 0,
        nullptr, nullptr, DM, DI);

    cudaStreamWaitEvent(0, eP1, 0);
}